// round 16
// baseline (speedup 1.0000x reference)
#include <cuda_runtime.h>
#include <cuda_bf16.h>

// Problem constants: pred [8,16,512,512] f32, target [8,512,512] int32
#define N_IMG   8
#define N_CLS   16
#define HW      262144            // 512*512
#define CHW     (N_CLS * HW)
#define HW4     (HW / 4)          // 65536 float4 groups per channel-plane
#define BPI     128               // blocks per image in main kernel
#define MAIN_BLOCKS (N_IMG * BPI) // 1024

// Per-block partials, class-major: for (c,img) fixed, the 128 block entries
// are contiguous -> final reduces them with one float4 per lane.
__device__ float        g_S[N_CLS][MAIN_BLOCKS];  // sum of logp_t per class
__device__ unsigned int g_C[N_CLS][MAIN_BLOCKS];  // pixel count per class

// ---------------------------------------------------------------------------
// Kernel 1: main pass — single pass over pred + target; weights not needed
// thanks to the decomposition num = sum_c w_c*S, den = sum_c w_c*C.
// Body (per thread, 2 groups of 4 pixels): 1 int4 target load + 16 float4
// channel loads in 2 batches of 8; exp-sum without max subtraction (logits
// are small); compare-select gather; lp = v_t - log(sum).
// Scatter: lp -> dynamically-indexed LOCAL array (LDL/FADD/STL, 4-cyc LSU
// floor — no atomics, no per-class select-adds). Counts -> nibble-packed
// register (8 increments, capacity 15).
// Epilogue: counts via proven R10 packed-SIMD warp reduce; S via 16
// shuffle trees; 16 threads plain-store the block row. No fences/atomics.
// ---------------------------------------------------------------------------
__global__ __launch_bounds__(256, 4) void dwce_main(const float* __restrict__ pred,
                                                    const int* __restrict__ target) {
    __shared__ float        sw_acc[8][17];  // [warp][class] (+pad)
    __shared__ unsigned int shc[8][8];      // [warp][packed count word]
    int tid = threadIdx.x;
    int w = tid >> 5, lane = tid & 31;

    float acc[N_CLS];                       // dynamic-indexed -> local memory
#pragma unroll
    for (int c = 0; c < N_CLS; c++) acc[c] = 0.0f;
    unsigned long long cnt = 0ull;

    int img = blockIdx.x >> 7;
    int blk = blockIdx.x & (BPI - 1);
    const float4* pv = (const float4*)(pred + (size_t)img * CHW);
    const int4*   tv = (const int4*)(target + (size_t)img * HW);

#pragma unroll
    for (int k = 0; k < 2; k++) {
        int g = k * 32768 + blk * 256 + tid;    // float4-group index in image
        int4 t4 = tv[g];
        int t0 = t4.x, t1 = t4.y, t2 = t4.z, t3 = t4.w;

        float4 s = make_float4(0.0f, 0.0f, 0.0f, 0.0f);
        float vt0 = 0.0f, vt1 = 0.0f, vt2 = 0.0f, vt3 = 0.0f;

#pragma unroll
        for (int cb = 0; cb < N_CLS; cb += 8) {
            float4 v[8];
#pragma unroll
            for (int j = 0; j < 8; j++) v[j] = pv[(cb + j) * HW4 + g];
#pragma unroll
            for (int j = 0; j < 8; j++) {
                int c = cb + j;
                if (c == t0) vt0 = v[j].x;
                if (c == t1) vt1 = v[j].y;
                if (c == t2) vt2 = v[j].z;
                if (c == t3) vt3 = v[j].w;
                s.x += __expf(v[j].x);
                s.y += __expf(v[j].y);
                s.z += __expf(v[j].z);
                s.w += __expf(v[j].w);
            }
        }

        float lp0 = vt0 - __logf(s.x);
        float lp1 = vt1 - __logf(s.y);
        float lp2 = vt2 - __logf(s.z);
        float lp3 = vt3 - __logf(s.w);

        cnt += (1ull << (t0 * 4)) + (1ull << (t1 * 4))
             + (1ull << (t2 * 4)) + (1ull << (t3 * 4));

        acc[t0] += lp0;
        acc[t1] += lp1;
        acc[t2] += lp2;
        acc[t3] += lp3;
    }

    // ---- counts: packed-SIMD warp reduce (R10 scheme; nibble <= 8) ----
    const unsigned long long NIB = 0x0F0F0F0F0F0F0F0Full;
    unsigned long long lo = cnt & NIB;          // byte j = class 2j
    unsigned long long hi = (cnt >> 4) & NIB;   // byte j = class 2j+1
    unsigned int a0 = (unsigned int)lo, a1 = (unsigned int)(lo >> 32);
    unsigned int a2 = (unsigned int)hi, a3 = (unsigned int)(hi >> 32);
#pragma unroll
    for (int o = 16; o >= 2; o >>= 1) {         // byte max 8*16 = 128 < 255
        a0 += __shfl_down_sync(0xFFFFFFFFu, a0, o);
        a1 += __shfl_down_sync(0xFFFFFFFFu, a1, o);
        a2 += __shfl_down_sync(0xFFFFFFFFu, a2, o);
        a3 += __shfl_down_sync(0xFFFFFFFFu, a3, o);
    }
    unsigned int b0 = a0 & 0x00FF00FFu, b1 = (a0 >> 8) & 0x00FF00FFu;
    unsigned int b2 = a1 & 0x00FF00FFu, b3 = (a1 >> 8) & 0x00FF00FFu;
    unsigned int b4 = a2 & 0x00FF00FFu, b5 = (a2 >> 8) & 0x00FF00FFu;
    unsigned int b6 = a3 & 0x00FF00FFu, b7 = (a3 >> 8) & 0x00FF00FFu;
    b0 += __shfl_down_sync(0xFFFFFFFFu, b0, 1);
    b1 += __shfl_down_sync(0xFFFFFFFFu, b1, 1);
    b2 += __shfl_down_sync(0xFFFFFFFFu, b2, 1);
    b3 += __shfl_down_sync(0xFFFFFFFFu, b3, 1);
    b4 += __shfl_down_sync(0xFFFFFFFFu, b4, 1);
    b5 += __shfl_down_sync(0xFFFFFFFFu, b5, 1);
    b6 += __shfl_down_sync(0xFFFFFFFFu, b6, 1);
    b7 += __shfl_down_sync(0xFFFFFFFFu, b7, 1);
    if (lane == 0) {
        shc[w][0] = b0; shc[w][1] = b1; shc[w][2] = b2; shc[w][3] = b3;
        shc[w][4] = b4; shc[w][5] = b5; shc[w][6] = b6; shc[w][7] = b7;
    }

    // ---- S: 16 shuffle trees over the local accumulators ----
#pragma unroll
    for (int c = 0; c < N_CLS; c++) {
        float v = acc[c];
#pragma unroll
        for (int o = 16; o > 0; o >>= 1)
            v += __shfl_down_sync(0xFFFFFFFFu, v, o);
        if (lane == 0) sw_acc[w][c] = v;
    }
    __syncthreads();

    // 16 threads: block totals, plain stores. Count extraction mapping
    // (proven R9/R10): word = (c&1)*4 + ((c>>3)&1)*2 + ((c>>1)&1),
    // u16 field = (c>>2)&1.
    if (tid < N_CLS) {
        int c = tid;
        float S = 0.0f;
#pragma unroll
        for (int j = 0; j < 8; j++) S += sw_acc[j][c];
        int wi = ((c & 1) << 2) + (((c >> 3) & 1) << 1) + ((c >> 1) & 1);
        int sftn = ((c >> 2) & 1) << 4;
        unsigned int tot = 0u;
#pragma unroll
        for (int j = 0; j < 8; j++) tot += (shc[j][wi] >> sftn) & 0xFFFFu;
        g_S[c][blockIdx.x] = S;
        g_C[c][blockIdx.x] = tot;
    }
}

// ---------------------------------------------------------------------------
// Kernel 2: finalize, 1024 threads. 128 (img,c) pairs; warp w handles pairs
// {w, w+32, w+64, w+96}. All 8 vector loads are issued BEFORE the shuffle
// trees (MLP -> one L2 round-trip). Then 16 threads derive class weights
// from global counts, 8 threads form per-image num/den, thread 0 writes.
// ---------------------------------------------------------------------------
__global__ __launch_bounds__(1024) void dwce_final(float* __restrict__ out) {
    __shared__ float sfS[128];      // [img*16 + c]
    __shared__ float sfC[128];
    __shared__ float sw[N_CLS];
    __shared__ float sr[N_IMG];
    int tid = threadIdx.x;
    int w = tid >> 5, lane = tid & 31;

    float4 fs[4];
    uint4  uc[4];
#pragma unroll
    for (int j = 0; j < 4; j++) {
        int p = w + 32 * j;                 // pair: img = p>>4, c = p&15
        int img = p >> 4, c = p & 15;
        fs[j] = ((const float4*)&g_S[c][img * BPI])[lane];
        uc[j] = ((const uint4*)&g_C[c][img * BPI])[lane];
    }
#pragma unroll
    for (int j = 0; j < 4; j++) {
        int p = w + 32 * j;
        float S = (fs[j].x + fs[j].y) + (fs[j].z + fs[j].w);
        float C = (float)((uc[j].x + uc[j].y) + (uc[j].z + uc[j].w));
#pragma unroll
        for (int o = 16; o > 0; o >>= 1) {
            S += __shfl_down_sync(0xFFFFFFFFu, S, o);
            C += __shfl_down_sync(0xFFFFFFFFu, C, o);
        }
        if (lane == 0) { sfS[p] = S; sfC[p] = C; }
    }
    __syncthreads();

    if (tid < N_CLS) {
        float tot = 0.0f;
#pragma unroll
        for (int i = 0; i < N_IMG; i++) tot += sfC[i * N_CLS + tid];
        sw[tid] = (tot > 0.0f) ? (1.0f / (16.0f * tot)) : 0.0f;
    }
    __syncthreads();

    if (tid < N_IMG) {
        float num = 0.0f, den = 0.0f;
#pragma unroll
        for (int c = 0; c < N_CLS; c++) {
            num += sw[c] * sfS[tid * N_CLS + c];
            den += sw[c] * sfC[tid * N_CLS + c];
        }
        sr[tid] = num / den;
    }
    __syncthreads();

    if (tid == 0) {
        float acc = 0.0f;
#pragma unroll
        for (int i = 0; i < N_IMG; i++) acc += sr[i];
        out[0] = -acc * (1.0f / (float)N_IMG);
    }
}

// ---------------------------------------------------------------------------
extern "C" void kernel_launch(void* const* d_in, const int* in_sizes, int n_in,
                              void* d_out, int out_size) {
    const float* pred   = (const float*)d_in[0];
    const int*   target = (const int*)d_in[1];
    // d_in[2] (weights) is ignored by the reference module.
    float* out = (float*)d_out;

    dwce_main<<<MAIN_BLOCKS, 256>>>(pred, target);
    dwce_final<<<1, 1024>>>(out);
}

// round 17
// speedup vs baseline: 1.2708x; 1.2708x over previous
#include <cuda_runtime.h>
#include <cuda_bf16.h>

// Problem constants: pred [8,16,512,512] f32, target [8,512,512] int32
#define N_IMG   8
#define N_CLS   16
#define HW      262144            // 512*512
#define NPIX    (N_IMG * HW)      // 2097152
#define CHW     (N_CLS * HW)
#define HW4     (HW / 4)          // 65536 float4 groups per channel-plane
#define BPI     128               // blocks per image in main kernel
#define MAIN_BLOCKS (N_IMG * BPI) // 1024
#define HIST_BLOCKS 256           // 256 blk * 512 thr * 4 int4 = NPIX/4

// Scratch (__device__ globals; no cudaMalloc allowed). All plain stores.
__device__ unsigned int g_hpart[HIST_BLOCKS][N_CLS]; // per-block class counts
__device__ float        g_pnum[MAIN_BLOCKS];         // per-block num partials
__device__ float        g_pden[MAIN_BLOCKS];         // per-block den partials

// ---------------------------------------------------------------------------
// Kernel 1 (R14-proven): per-class histogram of int32 targets.
// 512 threads/block, 16 px/thread as two 8-px nibble chains combined at byte
// level; SIMD warp reduction; 16 threads extract class totals; plain stores.
// Ends with a programmatic-launch-completion trigger so the PDL'd main
// kernel can overlap with it.
// ---------------------------------------------------------------------------
__global__ __launch_bounds__(512) void dwce_hist(const int* __restrict__ target) {
    __shared__ unsigned int sh[16][8];  // [warp][packed word]
    int tid = threadIdx.x;
    int w = tid >> 5, lane = tid & 31;

    const int4* tv = (const int4*)target;       // NPIX/4 = 524288 int4 groups
    int base = blockIdx.x * 2048 + tid;         // 2048 int4 per block

    int4 p0 = tv[base];
    int4 p1 = tv[base + 512];
    int4 p2 = tv[base + 1024];
    int4 p3 = tv[base + 1536];

    unsigned long long c1 =
          (1ull << (p0.x * 4)) + (1ull << (p0.y * 4))
        + (1ull << (p0.z * 4)) + (1ull << (p0.w * 4))
        + (1ull << (p1.x * 4)) + (1ull << (p1.y * 4))
        + (1ull << (p1.z * 4)) + (1ull << (p1.w * 4));
    unsigned long long c2 =
          (1ull << (p2.x * 4)) + (1ull << (p2.y * 4))
        + (1ull << (p2.z * 4)) + (1ull << (p2.w * 4))
        + (1ull << (p3.x * 4)) + (1ull << (p3.y * 4))
        + (1ull << (p3.z * 4)) + (1ull << (p3.w * 4));

    const unsigned long long NIB = 0x0F0F0F0F0F0F0F0Full;
    unsigned long long lo = (c1 & NIB) + (c2 & NIB);               // class 2j
    unsigned long long hi = ((c1 >> 4) & NIB) + ((c2 >> 4) & NIB); // class 2j+1

    unsigned int a0 = (unsigned int)lo, a1 = (unsigned int)(lo >> 32);
    unsigned int a2 = (unsigned int)hi, a3 = (unsigned int)(hi >> 32);

#pragma unroll
    for (int o = 16; o >= 4; o >>= 1) {         // byte max 16*8 = 128 < 255
        a0 += __shfl_down_sync(0xFFFFFFFFu, a0, o);
        a1 += __shfl_down_sync(0xFFFFFFFFu, a1, o);
        a2 += __shfl_down_sync(0xFFFFFFFFu, a2, o);
        a3 += __shfl_down_sync(0xFFFFFFFFu, a3, o);
    }

    unsigned int b0 = a0 & 0x00FF00FFu, b1 = (a0 >> 8) & 0x00FF00FFu;
    unsigned int b2 = a1 & 0x00FF00FFu, b3 = (a1 >> 8) & 0x00FF00FFu;
    unsigned int b4 = a2 & 0x00FF00FFu, b5 = (a2 >> 8) & 0x00FF00FFu;
    unsigned int b6 = a3 & 0x00FF00FFu, b7 = (a3 >> 8) & 0x00FF00FFu;

#pragma unroll
    for (int o = 2; o >= 1; o >>= 1) {          // u16 max 512 < 65535
        b0 += __shfl_down_sync(0xFFFFFFFFu, b0, o);
        b1 += __shfl_down_sync(0xFFFFFFFFu, b1, o);
        b2 += __shfl_down_sync(0xFFFFFFFFu, b2, o);
        b3 += __shfl_down_sync(0xFFFFFFFFu, b3, o);
        b4 += __shfl_down_sync(0xFFFFFFFFu, b4, o);
        b5 += __shfl_down_sync(0xFFFFFFFFu, b5, o);
        b6 += __shfl_down_sync(0xFFFFFFFFu, b6, o);
        b7 += __shfl_down_sync(0xFFFFFFFFu, b7, o);
    }

    if (lane == 0) {
        sh[w][0] = b0; sh[w][1] = b1; sh[w][2] = b2; sh[w][3] = b3;
        sh[w][4] = b4; sh[w][5] = b5; sh[w][6] = b6; sh[w][7] = b7;
    }
    __syncthreads();

    if (tid < N_CLS) {
        int c = tid;
        int wi = ((c & 1) << 2) + (((c >> 3) & 1) << 1) + ((c >> 1) & 1);
        int sftn = ((c >> 2) & 1) << 4;
        unsigned int tot = 0u;
#pragma unroll
        for (int j = 0; j < 16; j++) tot += (sh[j][wi] >> sftn) & 0xFFFFu;
        g_hpart[blockIdx.x][c] = tot;
    }
    __threadfence();
    cudaTriggerProgrammaticLaunchCompletion();
}

// ---------------------------------------------------------------------------
// Kernel 2: main pass (R13 body, 4 CTAs/SM), PDL-restructured:
// group 0 (no weights needed) -> cudaGridDependencySynchronize() -> weights
// prologue -> combine group 0 (same FP order as R13) -> group 1 inline.
// The 142 MB body of group 0 overlaps the histogram kernel.
// ---------------------------------------------------------------------------
__global__ __launch_bounds__(256, 4) void dwce_main(const float* __restrict__ pred,
                                                    const int* __restrict__ target) {
    __shared__ float sp[16][17];    // prologue partials (pad avoids conflicts)
    __shared__ float sh_w[N_CLS];
    __shared__ float sn[8], sd[8];
    int tid = threadIdx.x;

    int img = blockIdx.x >> 7;
    int blk = blockIdx.x & (BPI - 1);
    const float4* pv = (const float4*)(pred + (size_t)img * CHW);
    const int4*   tv = (const int4*)(target + (size_t)img * HW);

    // ---- group 0 (pre-sync: independent of histogram) ----
    float lp0, lp1, lp2, lp3;
    int h0, h1, h2, h3;
    {
        int g = blk * 256 + tid;                // k = 0 group index
        int4 t4 = tv[g];
        h0 = t4.x; h1 = t4.y; h2 = t4.z; h3 = t4.w;

        float4 s = make_float4(0.0f, 0.0f, 0.0f, 0.0f);
        float vt0 = 0.0f, vt1 = 0.0f, vt2 = 0.0f, vt3 = 0.0f;
#pragma unroll
        for (int cb = 0; cb < N_CLS; cb += 8) {
            float4 v[8];
#pragma unroll
            for (int j = 0; j < 8; j++) v[j] = pv[(cb + j) * HW4 + g];
#pragma unroll
            for (int j = 0; j < 8; j++) {
                int c = cb + j;
                if (c == h0) vt0 = v[j].x;
                if (c == h1) vt1 = v[j].y;
                if (c == h2) vt2 = v[j].z;
                if (c == h3) vt3 = v[j].w;
                s.x += __expf(v[j].x);
                s.y += __expf(v[j].y);
                s.z += __expf(v[j].z);
                s.w += __expf(v[j].w);
            }
        }
        lp0 = vt0 - __logf(s.x);
        lp1 = vt1 - __logf(s.y);
        lp2 = vt2 - __logf(s.z);
        lp3 = vt3 - __logf(s.w);
    }

    // ---- wait for histogram kernel, then derive class weights ----
    cudaGridDependencySynchronize();
    {
        int c = tid & 15, r = tid >> 4;         // r in [0,16): 16 rows each
        unsigned int s = 0;
#pragma unroll
        for (int j = 0; j < 16; j++) s += g_hpart[r + j * 16][c];
        sp[r][c] = (float)s;
    }
    __syncthreads();
    if (tid < N_CLS) {
        float tot = 0.0f;
#pragma unroll
        for (int r = 0; r < 16; r++) tot += sp[r][tid];
        sh_w[tid] = (tot > 0.0f) ? (1.0f / (16.0f * tot)) : 0.0f;
    }
    __syncthreads();

    // ---- combine group 0 (same FP order as R13) ----
    float num = 0.0f, den = 0.0f;
    {
        float w0 = sh_w[h0], w1 = sh_w[h1], w2 = sh_w[h2], w3 = sh_w[h3];
        num += w0 * lp0;
        num += w1 * lp1;
        num += w2 * lp2;
        num += w3 * lp3;
        den += (w0 + w1) + (w2 + w3);
    }

    // ---- group 1 (weighted inline, identical to R13 k=1) ----
    {
        int g = 32768 + blk * 256 + tid;
        int4 t4 = tv[g];
        int t0 = t4.x, t1 = t4.y, t2 = t4.z, t3 = t4.w;

        float4 s = make_float4(0.0f, 0.0f, 0.0f, 0.0f);
        float vt0 = 0.0f, vt1 = 0.0f, vt2 = 0.0f, vt3 = 0.0f;
#pragma unroll
        for (int cb = 0; cb < N_CLS; cb += 8) {
            float4 v[8];
#pragma unroll
            for (int j = 0; j < 8; j++) v[j] = pv[(cb + j) * HW4 + g];
#pragma unroll
            for (int j = 0; j < 8; j++) {
                int c = cb + j;
                if (c == t0) vt0 = v[j].x;
                if (c == t1) vt1 = v[j].y;
                if (c == t2) vt2 = v[j].z;
                if (c == t3) vt3 = v[j].w;
                s.x += __expf(v[j].x);
                s.y += __expf(v[j].y);
                s.z += __expf(v[j].z);
                s.w += __expf(v[j].w);
            }
        }

        float w0 = sh_w[t0], w1 = sh_w[t1], w2 = sh_w[t2], w3 = sh_w[t3];
        num += w0 * (vt0 - __logf(s.x));
        num += w1 * (vt1 - __logf(s.y));
        num += w2 * (vt2 - __logf(s.z));
        num += w3 * (vt3 - __logf(s.w));
        den += (w0 + w1) + (w2 + w3);
    }

    // ---- tail: block reduce, plain stores ----
#pragma unroll
    for (int o = 16; o > 0; o >>= 1) {
        num += __shfl_down_sync(0xFFFFFFFFu, num, o);
        den += __shfl_down_sync(0xFFFFFFFFu, den, o);
    }
    int w = tid >> 5, lane = tid & 31;
    if (lane == 0) { sn[w] = num; sd[w] = den; }
    __syncthreads();
    if (tid == 0) {
        float a = 0.0f, b = 0.0f;
#pragma unroll
        for (int i = 0; i < 8; i++) { a += sn[i]; b += sd[i]; }
        g_pnum[blockIdx.x] = a;
        g_pden[blockIdx.x] = b;
    }
}

// ---------------------------------------------------------------------------
// Kernel 3: finalize (R13-proven). Thread t loads blocks 4t..4t+3
// (contiguous, all in image t>>5); warp w covers exactly image w.
// ---------------------------------------------------------------------------
__global__ __launch_bounds__(256) void dwce_final(float* __restrict__ out) {
    __shared__ float sr[N_IMG];
    int tid = threadIdx.x;
    int w = tid >> 5, lane = tid & 31;

    float n = 0.0f, d = 0.0f;
#pragma unroll
    for (int j = 0; j < 4; j++) {
        int b = tid * 4 + j;
        n += g_pnum[b];
        d += g_pden[b];
    }
#pragma unroll
    for (int o = 16; o > 0; o >>= 1) {
        n += __shfl_down_sync(0xFFFFFFFFu, n, o);
        d += __shfl_down_sync(0xFFFFFFFFu, d, o);
    }
    if (lane == 0) sr[w] = n / d;
    __syncthreads();
    if (tid == 0) {
        float acc = 0.0f;
#pragma unroll
        for (int i = 0; i < N_IMG; i++) acc += sr[i];
        out[0] = -acc * (1.0f / (float)N_IMG);
    }
}

// ---------------------------------------------------------------------------
extern "C" void kernel_launch(void* const* d_in, const int* in_sizes, int n_in,
                              void* d_out, int out_size) {
    const float* pred   = (const float*)d_in[0];
    const int*   target = (const int*)d_in[1];
    // d_in[2] (weights) is ignored by the reference module.
    float* out = (float*)d_out;

    dwce_hist<<<HIST_BLOCKS, 512>>>(target);

    // Launch main with Programmatic Dependent Launch so it overlaps hist;
    // dwce_main gates its histogram read on cudaGridDependencySynchronize().
    cudaLaunchConfig_t cfg = {};
    cfg.gridDim = dim3(MAIN_BLOCKS, 1, 1);
    cfg.blockDim = dim3(256, 1, 1);
    cfg.dynamicSmemBytes = 0;
    cfg.stream = 0;
    cudaLaunchAttribute attr[1];
    attr[0].id = cudaLaunchAttributeProgrammaticStreamSerialization;
    attr[0].val.programmaticStreamSerializationAllowed = 1;
    cfg.attrs = attr;
    cfg.numAttrs = 1;
    cudaLaunchKernelEx(&cfg, dwce_main, pred, target);

    dwce_final<<<1, 256>>>(out);
}